// round 15
// baseline (speedup 1.0000x reference)
#include <cuda_runtime.h>
#include <math.h>
#include <stdint.h>

#define NROWS   8192
#define NCOLS   8192
#define G       1024            // grid; block b owns rows ≡ b (mod G)
#define RPB     8               // rows per block
#define D       4               // ring depth (stages)
#define THREADS 512
#define ROW_BYTES  (NCOLS * 4)  // 32768 per stage
#define HALF_BYTES (ROW_BYTES / 2)
#define DYN_SMEM   (D * ROW_BYTES)   // 128KB ring

// Scratch state. Invariant at entry: g_colsum all-zero, g_count zero; the last
// block restores both. g_rowsum/g_s1part fully overwritten each run.
__device__ float g_rowsum[NROWS];
__device__ float g_colsum[NCOLS];
__device__ float g_s1part[G];
__device__ unsigned int g_count;

__device__ __forceinline__ void mbar_init(uint32_t mb, uint32_t cnt) {
    asm volatile("mbarrier.init.shared.b64 [%0], %1;" :: "r"(mb), "r"(cnt) : "memory");
}
__device__ __forceinline__ void mbar_expect_tx(uint32_t mb, uint32_t bytes) {
    asm volatile("mbarrier.arrive.expect_tx.shared.b64 _, [%0], %1;"
                 :: "r"(mb), "r"(bytes) : "memory");
}
__device__ __forceinline__ void mbar_wait(uint32_t mb, uint32_t par) {
    asm volatile(
        "{\n\t.reg .pred P;\n\t"
        "W%=:\n\t"
        "mbarrier.try_wait.parity.acquire.cta.shared::cta.b64 P, [%0], %1, 0x989680;\n\t"
        "@!P bra W%=;\n\t}"
        :: "r"(mb), "r"(par) : "memory");
}
__device__ __forceinline__ void bulk_cp(uint32_t dst, const void* src,
                                        uint32_t bytes, uint32_t mb) {
    asm volatile(
        "cp.async.bulk.shared::cta.global.mbarrier::complete_tx::bytes [%0], [%1], %2, [%3];"
        :: "r"(dst), "l"(src), "r"(bytes), "r"(mb) : "memory");
}
__device__ __forceinline__ void fence_async_proxy() {
    asm volatile("fence.proxy.async.shared::cta;" ::: "memory");
}

__global__ __launch_bounds__(THREADS) void mi_tma_kernel(const float* __restrict__ ct,
                                                         float* __restrict__ out) {
    extern __shared__ __align__(1024) float ring[];      // [D][NCOLS]
    __shared__ float sp[D][THREADS];                     // per-thread row partials
    __shared__ uint64_t mbar_store[D];
    __shared__ float sw[16];
    __shared__ double sd[16];
    __shared__ unsigned int is_last;

    const int tid = threadIdx.x;
    const int w   = tid >> 5;
    const int l   = tid & 31;
    const int b   = blockIdx.x;

    const uint32_t ring_s = (uint32_t)__cvta_generic_to_shared(ring);
    const uint32_t mbar_s = (uint32_t)__cvta_generic_to_shared(mbar_store);

    if (tid == 0) {
        #pragma unroll
        for (int j = 0; j < D; ++j) mbar_init(mbar_s + 8 * j, 1);
        fence_async_proxy();
    }
    __syncthreads();

    // prologue: fill the ring (rows b, b+G, b+2G, b+3G)
    if (tid == 0) {
        #pragma unroll
        for (int s = 0; s < D; ++s) {
            const char* src = (const char*)ct + (size_t)(b + s * G) * ROW_BYTES;
            uint32_t mb = mbar_s + 8 * s;
            mbar_expect_tx(mb, ROW_BYTES);
            bulk_cp(ring_s + s * ROW_BYTES, src, HALF_BYTES, mb);
            bulk_cp(ring_s + s * ROW_BYTES + HALF_BYTES, src + HALF_BYTES, HALF_BYTES, mb);
        }
    }

    float ca[16];                         // cols: 4*tid + m + 2048*k
    #pragma unroll
    for (int i = 0; i < 16; ++i) ca[i] = 0.f;
    float s1a = 0.f, s1b = 0.f, s1c = 0.f, s1d = 0.f;

    #pragma unroll
    for (int s = 0; s < RPB; ++s) {
        const int slot = s % D;
        const uint32_t par = (s / D) & 1;
        mbar_wait(mbar_s + 8 * slot, par);

        const float4* buf = reinterpret_cast<const float4*>(ring + (size_t)slot * NCOLS);
        float rsum = 0.f;
        #pragma unroll
        for (int k = 0; k < 4; ++k) {
            float4 v = buf[tid + 512 * k];       // conflict-free
            float x = v.x, y = v.y, z = v.z, q = v.w;
            // inputs >= 0; nonzero values >= 2^-24 so fmaxf(x,1e-30)==x,
            // and x==0 contributes 0 * log2(1e-30) = 0.
            s1a = __fmaf_rn(x, __log2f(fmaxf(x, 1e-30f)), s1a);
            s1b = __fmaf_rn(y, __log2f(fmaxf(y, 1e-30f)), s1b);
            s1c = __fmaf_rn(z, __log2f(fmaxf(z, 1e-30f)), s1c);
            s1d = __fmaf_rn(q, __log2f(fmaxf(q, 1e-30f)), s1d);
            ca[k * 4 + 0] += x; ca[k * 4 + 1] += y;
            ca[k * 4 + 2] += z; ca[k * 4 + 3] += q;
            rsum += (x + y) + (z + q);
        }
        sp[slot][tid] = rsum;
        __syncthreads();                  // stage fully consumed; sp written

        // refill freed slot (engine writes start after all reads finished)
        if (tid == 0 && s + D < RPB) {
            const int ns = s + D;
            const char* src = (const char*)ct + (size_t)(b + ns * G) * ROW_BYTES;
            uint32_t mb = mbar_s + 8 * slot;
            mbar_expect_tx(mb, ROW_BYTES);
            bulk_cp(ring_s + slot * ROW_BYTES, src, HALF_BYTES, mb);
            bulk_cp(ring_s + slot * ROW_BYTES + HALF_BYTES, src + HALF_BYTES, HALF_BYTES, mb);
        }

        // warp s reduces this row in the shadow of the next stage's wait.
        // sp[slot] is not rewritten until stage s+D's consume, which is gated
        // by syncthreads this warp also participates in -> safe.
        if (w == s) {
            const float4* spv = reinterpret_cast<const float4*>(sp[slot]);
            float4 a0 = spv[l], a1 = spv[l + 32], a2 = spv[l + 64], a3 = spv[l + 96];
            float t = ((a0.x + a0.y) + (a0.z + a0.w)) + ((a1.x + a1.y) + (a1.z + a1.w))
                    + ((a2.x + a2.y) + (a2.z + a2.w)) + ((a3.x + a3.y) + (a3.z + a3.w));
            #pragma unroll
            for (int o = 16; o > 0; o >>= 1)
                t += __shfl_xor_sync(0xffffffffu, t, o);
            if (l == 0) g_rowsum[b + s * G] = t;   // unique owner: plain store
        }
    }

    // ---- column sums: 16 uniquely-owned cols per thread within block ----
    #pragma unroll
    for (int k = 0; k < 4; ++k)
        #pragma unroll
        for (int m = 0; m < 4; ++m)
            atomicAdd(&g_colsum[4 * tid + m + 2048 * k], ca[k * 4 + m]);

    // ---- S1 block partial -> plain store ----
    {
        float s1 = (s1a + s1b) + (s1c + s1d);
        #pragma unroll
        for (int o = 16; o > 0; o >>= 1)
            s1 += __shfl_xor_sync(0xffffffffu, s1, o);
        if (l == 0) sw[w] = s1;
        __syncthreads();
        if (tid == 0) {
            float t = 0.f;
            #pragma unroll
            for (int k = 0; k < 16; ++k) t += sw[k];
            g_s1part[b] = t;
        }
    }

    // ---- last-block completion ----
    __threadfence();
    __syncthreads();
    if (tid == 0) {
        unsigned int old = atomicAdd(&g_count, 1u);
        is_last = (old == (unsigned int)(G - 1)) ? 1u : 0u;
    }
    __syncthreads();
    if (!is_last) return;

    __threadfence();  // acquire: see all blocks' writes

    double acc = 0.0;
    for (int i = tid; i < NROWS; i += THREADS) {
        float s = g_rowsum[i];
        if (s > 0.f) acc -= (double)s * (double)__log2f(s);
    }
    for (int i = tid; i < NCOLS; i += THREADS) {
        float s = g_colsum[i];
        if (s > 0.f) acc -= (double)s * (double)__log2f(s);
        g_colsum[i] = 0.0f;               // restore invariant
    }
    for (int i = tid; i < G; i += THREADS)
        acc += (double)g_s1part[i];

    #pragma unroll
    for (int o = 16; o > 0; o >>= 1)
        acc += __shfl_xor_sync(0xffffffffu, acc, o);
    if (l == 0) sd[w] = acc;
    __syncthreads();
    if (tid == 0) {
        double a = 0.0;
        #pragma unroll
        for (int k = 0; k < 16; ++k) a += sd[k];
        out[0] = (float)a;
        g_count = 0u;                     // restore invariant
    }
}

extern "C" void kernel_launch(void* const* d_in, const int* in_sizes, int n_in,
                              void* d_out, int out_size) {
    const float* ct = (const float*)d_in[0];
    float* out = (float*)d_out;

    // Idempotent, not a stream op: capture-safe.
    cudaFuncSetAttribute(mi_tma_kernel,
                         cudaFuncAttributeMaxDynamicSharedMemorySize, DYN_SMEM);

    mi_tma_kernel<<<G, THREADS, DYN_SMEM>>>(ct, out);
}

// round 16
// speedup vs baseline: 1.9414x; 1.9414x over previous
#include <cuda_runtime.h>
#include <math.h>
#include <stdint.h>

#define NROWS 8192
#define NCOLS 8192
#define BC    1024             // cols per block
#define BR    64               // rows per block
#define GX    (NCOLS / BC)     // 8
#define GY    (NROWS / BR)     // 128
#define NBLK  (GX * GY)        // 1024
#define NST   (BR / 2)         // 32 stages of 2 rows
#define D     8                // ring depth
#define STAGE_FLOATS 2048      // 2 rows x 1024 cols = 8KB
#define STAGE_BYTES  (STAGE_FLOATS * 4)
#define ROWSEG_BYTES (BC * 4)  // 4KB per row segment
#define DYN_SMEM (D * STAGE_BYTES)   // 64KB

// Scratch state. Invariant: all-zero at entry; last block restores zeros.
__device__ float g_rowsum[NROWS];
__device__ float g_colsum[NCOLS];
__device__ float g_s1part[NBLK];
__device__ unsigned int g_count;

__device__ __forceinline__ void mbar_init(uint32_t mb, uint32_t cnt) {
    asm volatile("mbarrier.init.shared.b64 [%0], %1;" :: "r"(mb), "r"(cnt) : "memory");
}
__device__ __forceinline__ void mbar_expect_tx(uint32_t mb, uint32_t bytes) {
    asm volatile("mbarrier.arrive.expect_tx.shared.b64 _, [%0], %1;"
                 :: "r"(mb), "r"(bytes) : "memory");
}
__device__ __forceinline__ void mbar_wait(uint32_t mb, uint32_t par) {
    asm volatile(
        "{\n\t.reg .pred P;\n\t"
        "W%=:\n\t"
        "mbarrier.try_wait.parity.acquire.cta.shared::cta.b64 P, [%0], %1, 0x989680;\n\t"
        "@!P bra W%=;\n\t}"
        :: "r"(mb), "r"(par) : "memory");
}
__device__ __forceinline__ void bulk_cp(uint32_t dst, const void* src,
                                        uint32_t bytes, uint32_t mb) {
    asm volatile(
        "cp.async.bulk.shared::cta.global.mbarrier::complete_tx::bytes [%0], [%1], %2, [%3];"
        :: "r"(dst), "l"(src), "r"(bytes), "r"(mb) : "memory");
}
__device__ __forceinline__ void fence_async_proxy() {
    asm volatile("fence.proxy.async.shared::cta;" ::: "memory");
}

__global__ __launch_bounds__(256) void mi_tma_kernel(const float* __restrict__ ct,
                                                     float* __restrict__ out) {
    extern __shared__ __align__(128) float ring[];   // [D][STAGE_FLOATS]
    __shared__ uint64_t mbar_store[D];
    __shared__ float sp[BR][8];                      // [local row][warp] partials
    __shared__ float sw[8];
    __shared__ double sd[8];
    __shared__ unsigned int is_last;

    const int tid = threadIdx.x;
    const int w   = tid >> 5;
    const int l   = tid & 31;
    const int c0  = blockIdx.x * BC;
    const int r0  = blockIdx.y * BR;

    const uint32_t ring_s = (uint32_t)__cvta_generic_to_shared(ring);
    const uint32_t mbar_s = (uint32_t)__cvta_generic_to_shared(mbar_store);
    const char* gbase = (const char*)(ct + (size_t)r0 * NCOLS + c0);

    if (tid == 0) {
        #pragma unroll
        for (int j = 0; j < D; ++j) mbar_init(mbar_s + 8 * j, 1);
        fence_async_proxy();
    }
    __syncthreads();

    // prologue: fill the 8-stage ring (rows r0+2s, r0+2s+1 per stage)
    if (tid == 0) {
        #pragma unroll
        for (int s = 0; s < D; ++s) {
            const char* src = gbase + (size_t)(2 * s) * NCOLS * 4;
            uint32_t mb = mbar_s + 8 * s;
            mbar_expect_tx(mb, STAGE_BYTES);
            bulk_cp(ring_s + s * STAGE_BYTES, src, ROWSEG_BYTES, mb);
            bulk_cp(ring_s + s * STAGE_BYTES + ROWSEG_BYTES,
                    src + (size_t)NCOLS * 4, ROWSEG_BYTES, mb);
        }
    }

    float ca0 = 0.f, ca1 = 0.f, ca2 = 0.f, ca3 = 0.f;   // cols c0+4*tid+m
    float s1a = 0.f, s1b = 0.f, s1c = 0.f, s1d = 0.f;

    for (int s = 0; s < NST; ++s) {
        const int slot = s & (D - 1);
        mbar_wait(mbar_s + 8 * slot, (s >> 3) & 1);

        const float4* buf = reinterpret_cast<const float4*>(ring + slot * STAGE_FLOATS);
        float4 va = buf[tid];            // row 2s
        float4 vb = buf[tid + 256];      // row 2s+1

        // inputs >= 0; nonzero values >= 2^-24 so fmaxf(x,1e-30)==x,
        // and x==0 contributes 0 * log2(1e-30) = 0.
        s1a = __fmaf_rn(va.x, __log2f(fmaxf(va.x, 1e-30f)), s1a);
        s1b = __fmaf_rn(va.y, __log2f(fmaxf(va.y, 1e-30f)), s1b);
        s1c = __fmaf_rn(va.z, __log2f(fmaxf(va.z, 1e-30f)), s1c);
        s1d = __fmaf_rn(va.w, __log2f(fmaxf(va.w, 1e-30f)), s1d);
        s1a = __fmaf_rn(vb.x, __log2f(fmaxf(vb.x, 1e-30f)), s1a);
        s1b = __fmaf_rn(vb.y, __log2f(fmaxf(vb.y, 1e-30f)), s1b);
        s1c = __fmaf_rn(vb.z, __log2f(fmaxf(vb.z, 1e-30f)), s1c);
        s1d = __fmaf_rn(vb.w, __log2f(fmaxf(vb.w, 1e-30f)), s1d);

        ca0 += va.x + vb.x; ca1 += va.y + vb.y;
        ca2 += va.z + vb.z; ca3 += va.w + vb.w;

        float ra = (va.x + va.y) + (va.z + va.w);
        float rb = (vb.x + vb.y) + (vb.z + vb.w);
        #pragma unroll
        for (int o = 16; o > 0; o >>= 1) {
            ra += __shfl_xor_sync(0xffffffffu, ra, o);
            rb += __shfl_xor_sync(0xffffffffu, rb, o);
        }
        if (l == 0) { sp[2 * s][w] = ra; sp[2 * s + 1][w] = rb; }

        __syncthreads();                 // stage fully consumed

        if (tid == 0 && s + D < NST) {
            const int ns = s + D;
            const char* src = gbase + (size_t)(2 * ns) * NCOLS * 4;
            uint32_t mb = mbar_s + 8 * slot;
            mbar_expect_tx(mb, STAGE_BYTES);
            bulk_cp(ring_s + slot * STAGE_BYTES, src, ROWSEG_BYTES, mb);
            bulk_cp(ring_s + slot * STAGE_BYTES + ROWSEG_BYTES,
                    src + (size_t)NCOLS * 4, ROWSEG_BYTES, mb);
        }
    }

    // ---- row sums: thread t<64 sums its row's 8 warp-partials ----
    if (tid < BR) {
        float t = 0.f;
        #pragma unroll
        for (int k = 0; k < 8; ++k) t += sp[tid][k];
        atomicAdd(&g_rowsum[r0 + tid], t);
    }

    // ---- column sums: thread owns 4 fixed cols -> direct atomics ----
    atomicAdd(&g_colsum[c0 + 4 * tid + 0], ca0);
    atomicAdd(&g_colsum[c0 + 4 * tid + 1], ca1);
    atomicAdd(&g_colsum[c0 + 4 * tid + 2], ca2);
    atomicAdd(&g_colsum[c0 + 4 * tid + 3], ca3);

    // ---- S1 block partial -> plain store ----
    {
        float s1 = (s1a + s1b) + (s1c + s1d);
        #pragma unroll
        for (int o = 16; o > 0; o >>= 1)
            s1 += __shfl_xor_sync(0xffffffffu, s1, o);
        if (l == 0) sw[w] = s1;
        __syncthreads();
        if (tid == 0) {
            float t = 0.f;
            #pragma unroll
            for (int k = 0; k < 8; ++k) t += sw[k];
            g_s1part[blockIdx.y * gridDim.x + blockIdx.x] = t;
        }
    }

    // ---- last-block completion ----
    __threadfence();
    __syncthreads();
    if (tid == 0) {
        unsigned int old = atomicAdd(&g_count, 1u);
        is_last = (old == (unsigned int)(NBLK - 1)) ? 1u : 0u;
    }
    __syncthreads();
    if (!is_last) return;

    __threadfence();  // acquire: see all blocks' writes

    double acc = 0.0;
    for (int i = tid; i < NROWS; i += 256) {
        float s = g_rowsum[i];
        if (s > 0.f) acc -= (double)s * (double)__log2f(s);
        g_rowsum[i] = 0.0f;               // restore invariant
    }
    for (int i = tid; i < NCOLS; i += 256) {
        float s = g_colsum[i];
        if (s > 0.f) acc -= (double)s * (double)__log2f(s);
        g_colsum[i] = 0.0f;               // restore invariant
    }
    for (int i = tid; i < NBLK; i += 256)
        acc += (double)g_s1part[i];

    #pragma unroll
    for (int o = 16; o > 0; o >>= 1)
        acc += __shfl_xor_sync(0xffffffffu, acc, o);
    if (l == 0) sd[w] = acc;
    __syncthreads();
    if (tid == 0) {
        double a = 0.0;
        #pragma unroll
        for (int k = 0; k < 8; ++k) a += sd[k];
        out[0] = (float)a;
        g_count = 0u;                     // restore invariant
    }
}

extern "C" void kernel_launch(void* const* d_in, const int* in_sizes, int n_in,
                              void* d_out, int out_size) {
    const float* ct = (const float*)d_in[0];
    float* out = (float*)d_out;

    // Idempotent, not a stream op: capture-safe.
    cudaFuncSetAttribute(mi_tma_kernel,
                         cudaFuncAttributeMaxDynamicSharedMemorySize, DYN_SMEM);

    dim3 grid(GX, GY);
    mi_tma_kernel<<<grid, 256, DYN_SMEM>>>(ct, out);
}